// round 14
// baseline (speedup 1.0000x reference)
#include <cuda_runtime.h>
#include <cstdint>

#define B 8
#define T 1024
#define E 128
#define H 8
#define HB (H*B)
#define SCALE 0.08838834764831845f   // 1/sqrt(128)
#define NEGV (-1e9f)
#define QT 16
#define CH 128
#define KS 132                        // padded K row stride (floats)
#define QS 132                        // padded Q row stride (floats)
#define SS 1028                       // padded score row stride (floats)
#define THR 512
#define PKS 132                       // proj x tile stride
#define PWS 68                        // proj wraw stride ([k][n] layout)

// ---------------- scratch (static device globals; no allocs allowed) --------
__device__ float g_q[HB * T * E];
__device__ float g_k[HB * T * E];
__device__ float g_v[HB * T * E];
__device__ float g_sel[B * H];

// ---------------- helpers ----------------------------------------------------
__device__ __forceinline__ void cpa16(uint32_t dst, const void* src) {
    asm volatile("cp.async.cg.shared.global [%0], [%1], 16;\n" :: "r"(dst), "l"(src));
}
__device__ __forceinline__ void cpa_commit() {
    asm volatile("cp.async.commit_group;\n");
}
__device__ __forceinline__ void cpa_wait0() {
    asm volatile("cp.async.wait_group 0;\n");
}
__device__ __forceinline__ uint32_t tf32_rna(float x) {
    uint32_t r;
    asm("cvt.rna.tf32.f32 %0, %1;" : "=r"(r) : "f"(x));
    return r;
}
__device__ __forceinline__ void mma_tf32(float& c0, float& c1, float& c2, float& c3,
                                         uint32_t a0, uint32_t a1, uint32_t a2, uint32_t a3,
                                         uint32_t b0, uint32_t b1) {
    asm("mma.sync.aligned.m16n8k8.row.col.f32.tf32.tf32.f32 "
        "{%0,%1,%2,%3}, {%4,%5,%6,%7}, {%8,%9}, {%0,%1,%2,%3};"
        : "+f"(c0), "+f"(c1), "+f"(c2), "+f"(c3)
        : "r"(a0), "r"(a1), "r"(a2), "r"(a3), "r"(b0), "r"(b1));
}

// ---------------- projection GEMM via 3xTF32 mma (unchanged, 137us) ----------
__global__ void __launch_bounds__(256) proj_mma_kernel(const float* __restrict__ x,
                                                       const float* __restrict__ wq,
                                                       const float* __restrict__ wk,
                                                       const float* __restrict__ wv) {
    const float* w;
    float* out;
    if (blockIdx.z == 0)      { w = wq; out = g_q; }
    else if (blockIdx.z == 1) { w = wk; out = g_k; }
    else                      { w = wv; out = g_v; }

    extern __shared__ float psm[];
    float* xs   = psm;                 // 64 * PKS
    float* wraw = psm + 64 * PKS;      // 128 * PWS ([k][n])

    const int tid  = threadIdx.x;
    const int wid  = tid >> 5;
    const int lane = tid & 31;
    const int mw   = wid >> 1;
    const int nw   = wid & 1;
    const int g    = lane >> 2;
    const int tig  = lane & 3;
    const int m0 = blockIdx.y * 64;
    const int n0 = blockIdx.x * 64;

    #pragma unroll
    for (int i = 0; i < 8; i++) {
        int f = tid + i * 256;
        int row = f >> 5, c4 = f & 31;
        *(float4*)&xs[row * PKS + c4 * 4] =
            *(const float4*)(x + (size_t)(m0 + row) * 128 + c4 * 4);
    }
    #pragma unroll
    for (int i = 0; i < 8; i++) {
        int f = tid + i * 256;
        int k = f >> 4, c = f & 15;
        *(float4*)&wraw[k * PWS + c * 4] =
            *(const float4*)(w + (size_t)k * 1024 + n0 + c * 4);
    }
    __syncthreads();

    float c0[4], c1[4], c2[4], c3[4];
    #pragma unroll
    for (int t8 = 0; t8 < 4; t8++) { c0[t8] = c1[t8] = c2[t8] = c3[t8] = 0.f; }

    const float* Ar0 = xs + (mw * 16 + g) * PKS + tig;
    const float* Ar1 = xs + (mw * 16 + g + 8) * PKS + tig;
    const int nbase = nw * 32 + g;

    #pragma unroll
    for (int e0 = 0; e0 < 128; e0 += 8) {
        float a0f = Ar0[e0], a1f = Ar1[e0], a2f = Ar0[e0 + 4], a3f = Ar1[e0 + 4];
        uint32_t ah0 = tf32_rna(a0f), ah1 = tf32_rna(a1f);
        uint32_t ah2 = tf32_rna(a2f), ah3 = tf32_rna(a3f);
        uint32_t al0 = tf32_rna(a0f - __uint_as_float(ah0));
        uint32_t al1 = tf32_rna(a1f - __uint_as_float(ah1));
        uint32_t al2 = tf32_rna(a2f - __uint_as_float(ah2));
        uint32_t al3 = tf32_rna(a3f - __uint_as_float(ah3));
        const float* Wr0 = wraw + (tig + e0) * PWS + nbase;
        const float* Wr1 = wraw + (tig + 4 + e0) * PWS + nbase;
        #pragma unroll
        for (int t8 = 0; t8 < 4; t8++) {
            float b0f = Wr0[t8 * 8];
            float b1f = Wr1[t8 * 8];
            uint32_t bh0 = tf32_rna(b0f), bh1 = tf32_rna(b1f);
            uint32_t bl0 = tf32_rna(b0f - __uint_as_float(bh0));
            uint32_t bl1 = tf32_rna(b1f - __uint_as_float(bh1));
            mma_tf32(c0[t8], c1[t8], c2[t8], c3[t8], ah0, ah1, ah2, ah3, bl0, bl1);
            mma_tf32(c0[t8], c1[t8], c2[t8], c3[t8], al0, al1, al2, al3, bh0, bh1);
            mma_tf32(c0[t8], c1[t8], c2[t8], c3[t8], ah0, ah1, ah2, ah3, bh0, bh1);
        }
    }

    const int bb = m0 >> 10;
    const int tbase = (m0 & 1023) + mw * 16;
    #pragma unroll
    for (int t8 = 0; t8 < 4; t8++) {
        int n = n0 + nw * 32 + t8 * 8 + 2 * tig;
        int hh = n >> 7, e = n & 127;
        float* o0 = out + ((size_t)(hh * B + bb) * T + tbase + g) * E + e;
        float* o1 = out + ((size_t)(hh * B + bb) * T + tbase + g + 8) * E + e;
        *(float2*)o0 = make_float2(c0[t8], c1[t8]);
        *(float2*)o1 = make_float2(c2[t8], c3[t8]);
    }
}

// ---------------- head-gate softmax (unchanged) ------------------------------
__global__ void __launch_bounds__(128) sel_kernel(const float* __restrict__ x,
                                                  const float* __restrict__ w_s,
                                                  const float* __restrict__ b_s) {
    const int b = blockIdx.x;
    const int tid = threadIdx.x;
    __shared__ float mean_sh[128];
    __shared__ float logit_sh[8];

    const float* xb = x + (size_t)b * T * E;
    float s = 0.f;
    for (int t = 0; t < T; t++) s += xb[(size_t)t * E + tid];
    mean_sh[tid] = s * (1.0f / 1024.0f);
    __syncthreads();
    if (tid < H) {
        float l = b_s[tid];
        const float* wr = w_s + tid * E;
        #pragma unroll 4
        for (int e = 0; e < E; e++) l = fmaf(mean_sh[e], wr[e], l);
        logit_sh[tid] = l;
    }
    __syncthreads();
    if (tid == 0) {
        float mx = logit_sh[0];
        for (int h = 1; h < H; h++) mx = fmaxf(mx, logit_sh[h]);
        float ex[H]; float den = 0.f;
        for (int h = 0; h < H; h++) { ex[h] = expf(logit_sh[h] - mx); den += ex[h]; }
        float inv = 1.0f / den;
        for (int h = 0; h < H; h++) g_sel[b * H + h] = ex[h] * inv;
    }
}

// ---------------- fused attention: 3 indep MMA chains + head-ahead prefetch --
__global__ void __launch_bounds__(THR) attn7_kernel(const int* __restrict__ mask,
                                                    float* __restrict__ y) {
    extern __shared__ float sm[];
    float*    Kb0    = sm;                          // 2 buffers of CH*KS
    float*    s_sh   = sm + 2 * CH * KS;
    float*    Qhi    = s_sh + QT * SS;
    float*    Qlo    = Qhi + QT * QS;
    uint32_t* mb     = (uint32_t*)(Qlo + QT * QS);  // 512 words
    float*    tau_sh = (float*)(mb + 512);
    float*    sel_sh = tau_sh + 16;
    int*      qscan  = (int*)(sel_sh + 8);
    int*      full_sh= qscan + 17;
    int*      flat   = (int*)(Kb0 + CH * KS);       // pinned to buffer 1 region

    const int b    = blockIdx.y;
    const int q0   = blockIdx.x * QT;
    const int tid  = threadIdx.x;
    const int krow = tid & 127;
    const int qh   = tid >> 7;
    const int wid  = tid >> 5;
    const int lane = tid & 31;
    const int g    = lane >> 2;
    const int tig  = lane & 3;
    const int kb   = wid * 8;

    float out_reg[4] = {0.f, 0.f, 0.f, 0.f};
    if (tid < H) sel_sh[tid] = g_sel[b * H + tid];

    // ---- mask bitwords (bit set = masked) ----
    {
        int q = tid >> 5, wk = tid & 31;
        const int4* p = (const int4*)(mask + ((size_t)b * T + q0 + q) * T + wk * 32);
        uint32_t word = 0;
        #pragma unroll
        for (int i = 0; i < 8; i++) {
            int4 v = p[i];
            word |= (uint32_t)(v.x != 0) << (i * 4 + 0);
            word |= (uint32_t)(v.y != 0) << (i * 4 + 1);
            word |= (uint32_t)(v.z != 0) << (i * 4 + 2);
            word |= (uint32_t)(v.w != 0) << (i * 4 + 3);
        }
        mb[tid] = word;
    }
    __syncthreads();
    if (tid < QT) {
        int c = 0;
        #pragma unroll
        for (int i = 0; i < 32; i++) c += __popc(mb[tid * 32 + i]);
        full_sh[tid] = (c == 1024);
    }

    // prefetch head 0 chunk 0 into buffer 0
    {
        const float4* src = (const float4*)(g_k + (size_t)b * T * E);
        uint32_t dbase = (uint32_t)__cvta_generic_to_shared(Kb0);
        #pragma unroll
        for (int i = 0; i < 8; i++) {
            int f = tid + i * THR;
            int r = f >> 5, c4 = f & 31;
            cpa16(dbase + (uint32_t)(r * KS + c4 * 4) * 4, src + f);
        }
        cpa_commit();
    }

    for (int h = 0; h < H; h++) {
        const size_t hb = (size_t)(h * B + b);
        const float* Kg = g_k + hb * T * E;

        // Q tile -> tf32 hi/lo decomposition (once per head)
        {
            int j = tid >> 5, c4 = tid & 31;
            float4 qv = ((const float4*)(g_q + (hb * T + q0 + j) * E))[c4];
            float4 hi, lo;
            hi.x = __uint_as_float(tf32_rna(qv.x)); lo.x = __uint_as_float(tf32_rna(qv.x - hi.x));
            hi.y = __uint_as_float(tf32_rna(qv.y)); lo.y = __uint_as_float(tf32_rna(qv.y - hi.y));
            hi.z = __uint_as_float(tf32_rna(qv.z)); lo.z = __uint_as_float(tf32_rna(qv.z - hi.z));
            hi.w = __uint_as_float(tf32_rna(qv.w)); lo.w = __uint_as_float(tf32_rna(qv.w - hi.w));
            *(float4*)(Qhi + j * QS + c4 * 4) = hi;
            *(float4*)(Qlo + j * QS + c4 * 4) = lo;
        }

        for (int c = 0; c < 8; c++) {
            cpa_wait0();
            __syncthreads();          // chunk c visible; other buffer free
            if (c < 7) {              // prefetch next chunk
                const float4* src = (const float4*)(Kg + (size_t)(c + 1) * CH * E);
                float* dstb = Kb0 + ((c + 1) & 1) * (CH * KS);
                uint32_t dbase = (uint32_t)__cvta_generic_to_shared(dstb);
                #pragma unroll
                for (int i = 0; i < 8; i++) {
                    int f = tid + i * THR;
                    int r = f >> 5, c4 = f & 31;
                    cpa16(dbase + (uint32_t)(r * KS + c4 * 4) * 4, src + f);
                }
                cpa_commit();
            }

            // ---- 3xTF32 mma with 3 INDEPENDENT C chains (hh, hl, lh) ----
            const float* Kc  = Kb0 + (c & 1) * (CH * KS);
            const float* Br  = Kc + (kb + g) * KS + tig;
            const float* Ah0 = Qhi + g * QS + tig;
            const float* Ah1 = Qhi + (g + 8) * QS + tig;
            const float* Al0 = Qlo + g * QS + tig;
            const float* Al1 = Qlo + (g + 8) * QS + tig;
            float hh0 = 0.f, hh1 = 0.f, hh2 = 0.f, hh3 = 0.f;
            float hl0 = 0.f, hl1 = 0.f, hl2 = 0.f, hl3 = 0.f;
            float lh0 = 0.f, lh1 = 0.f, lh2 = 0.f, lh3 = 0.f;
            #pragma unroll
            for (int e0 = 0; e0 < 128; e0 += 8) {
                uint32_t ah0 = __float_as_uint(Ah0[e0]);
                uint32_t ah1 = __float_as_uint(Ah1[e0]);
                uint32_t ah2 = __float_as_uint(Ah0[e0 + 4]);
                uint32_t ah3 = __float_as_uint(Ah1[e0 + 4]);
                uint32_t al0 = __float_as_uint(Al0[e0]);
                uint32_t al1 = __float_as_uint(Al1[e0]);
                uint32_t al2 = __float_as_uint(Al0[e0 + 4]);
                uint32_t al3 = __float_as_uint(Al1[e0 + 4]);
                float b0f = Br[e0], b1f = Br[e0 + 4];
                uint32_t bh0 = tf32_rna(b0f), bh1 = tf32_rna(b1f);
                uint32_t bl0 = tf32_rna(b0f - __uint_as_float(bh0));
                uint32_t bl1 = tf32_rna(b1f - __uint_as_float(bh1));
                mma_tf32(hl0, hl1, hl2, hl3, ah0, ah1, ah2, ah3, bl0, bl1); // hi*lo
                mma_tf32(lh0, lh1, lh2, lh3, al0, al1, al2, al3, bh0, bh1); // lo*hi
                mma_tf32(hh0, hh1, hh2, hh3, ah0, ah1, ah2, ah3, bh0, bh1); // hi*hi
            }
            float c0 = hh0 + (hl0 + lh0);
            float c1 = hh1 + (hl1 + lh1);
            float c2 = hh2 + (hl2 + lh2);
            float c3 = hh3 + (hl3 + lh3);

            // epilogue: C rows = q (g, g+8), cols = k (kb+2tig, +1); mask + scale
            {
                const int kg0 = c * CH + kb + 2 * tig;
                const int kg1 = kg0 + 1;
                const int qa  = g;
                const int qb  = g + 8;
                const int wix0 = kg0 >> 5, bix0 = kg0 & 31;
                const int wix1 = kg1 >> 5, bix1 = kg1 & 31;
                uint32_t wa0 = mb[qa * 32 + wix0];
                uint32_t wa1 = mb[qa * 32 + wix1];
                uint32_t wb0 = mb[qb * 32 + wix0];
                uint32_t wb1 = mb[qb * 32 + wix1];
                s_sh[qa * SS + kg0] = ((wa0 >> bix0) & 1u) ? NEGV : c0 * SCALE;
                s_sh[qa * SS + kg1] = ((wa1 >> bix1) & 1u) ? NEGV : c1 * SCALE;
                s_sh[qb * SS + kg0] = ((wb0 >> bix0) & 1u) ? NEGV : c2 * SCALE;
                s_sh[qb * SS + kg1] = ((wb1 >> bix1) & 1u) ? NEGV : c3 * SCALE;
            }
        }
        __syncthreads();              // all scores in s_sh; both K buffers free

        // ---- early prefetch: next head's chunk 0 into buffer 0 ----
        if (h < H - 1) {
            const float4* src = (const float4*)(g_k + (size_t)((h + 1) * B + b) * T * E);
            uint32_t dbase = (uint32_t)__cvta_generic_to_shared(Kb0);
            #pragma unroll
            for (int i = 0; i < 8; i++) {
                int f = tid + i * THR;
                int r = f >> 5, c4 = f & 31;
                cpa16(dbase + (uint32_t)(r * KS + c4 * 4) * 4, src + f);
            }
            cpa_commit();
        }

        // ---- load this warp's score row into registers (one pass) ----
        float4 vr[8];
        {
            const float4* s4 = (const float4*)(s_sh + wid * SS);
            #pragma unroll
            for (int i = 0; i < 8; i++) vr[i] = s4[lane + i * 32];
        }

        // ---- sparsemax (Michelot), register-resident ----
        float tau;
        int excl, cnt;
        {
            if (full_sh[wid]) {
                tau = 3.0e38f;
            } else {
                tau = -1.0e8f;
                int prev = -1;
                for (int it = 0; it < 64; it++) {
                    float ls = 0.f; int lc = 0;
                    #pragma unroll
                    for (int i = 0; i < 8; i++) {
                        float4 v = vr[i];
                        if (v.x > tau) { ls += v.x; lc++; }
                        if (v.y > tau) { ls += v.y; lc++; }
                        if (v.z > tau) { ls += v.z; lc++; }
                        if (v.w > tau) { ls += v.w; lc++; }
                    }
                    #pragma unroll
                    for (int o = 16; o; o >>= 1) {
                        ls += __shfl_xor_sync(0xffffffffu, ls, o);
                        lc += __shfl_xor_sync(0xffffffffu, lc, o);
                    }
                    if (lc == prev || lc == 0) break;
                    tau = (ls - 1.f) / (float)lc;
                    prev = lc;
                }
            }
            if (lane == 0) tau_sh[wid] = tau;

            cnt = 0;
            #pragma unroll
            for (int i = 0; i < 8; i++) {
                float4 v = vr[i];
                cnt += (v.x > tau) + (v.y > tau) + (v.z > tau) + (v.w > tau);
            }
            int incl = cnt;
            #pragma unroll
            for (int o = 1; o < 32; o <<= 1) {
                int t = __shfl_up_sync(0xffffffffu, incl, o);
                if (lane >= o) incl += t;
            }
            excl = incl - cnt;
            if (lane == 31) qscan[wid + 1] = incl;
        }
        __syncthreads();
        if (tid == 0) {
            qscan[0] = 0;
            #pragma unroll
            for (int i = 1; i <= 16; i++) qscan[i] += qscan[i - 1];
        }
        __syncthreads();

        // ---- flat support list (buffer-1 region; k indices, q-contiguous) ----
        if (cnt > 0) {
            int off = qscan[wid] + excl;
            #pragma unroll
            for (int i = 0; i < 8; i++) {
                int kbase = (lane + i * 32) * 4;
                float4 v = vr[i];
                if (v.x > tau) flat[off++] = kbase;
                if (v.y > tau) flat[off++] = kbase + 1;
                if (v.z > tau) flat[off++] = kbase + 2;
                if (v.w > tau) flat[off++] = kbase + 3;
            }
        }
        __syncthreads();

        // ---- sparse AV: 4-way ILP register accumulation ----
        {
            const float selh = sel_sh[h];
            const float* Vg = g_v + hb * T * E + krow;   // krow == e
            #pragma unroll
            for (int j = 0; j < 4; j++) {
                int q = qh * 4 + j;
                float tq = tau_sh[q];
                int s = qscan[q], e = qscan[q + 1];
                const float* sq = s_sh + q * SS;
                float a0 = 0.f, a1 = 0.f, a2 = 0.f, a3 = 0.f;
                int i = s;
                for (; i + 4 <= e; i += 4) {
                    int k0 = flat[i], k1 = flat[i + 1], k2 = flat[i + 2], k3 = flat[i + 3];
                    float p0 = sq[k0] - tq;
                    float p1 = sq[k1] - tq;
                    float p2 = sq[k2] - tq;
                    float p3 = sq[k3] - tq;
                    a0 = fmaf(p0, Vg[(size_t)k0 * E], a0);
                    a1 = fmaf(p1, Vg[(size_t)k1 * E], a1);
                    a2 = fmaf(p2, Vg[(size_t)k2 * E], a2);
                    a3 = fmaf(p3, Vg[(size_t)k3 * E], a3);
                }
                for (; i < e; i++) {
                    int k0 = flat[i];
                    a0 = fmaf(sq[k0] - tq, Vg[(size_t)k0 * E], a0);
                }
                out_reg[j] = fmaf(selh, (a0 + a1) + (a2 + a3), out_reg[j]);
            }
        }
        __syncthreads();   // flat, s_sh, Qhi/Qlo reused next head
    }

    // ---- epilogue: direct global store ----
    float* yb = y + ((size_t)b * T + q0) * E;
    #pragma unroll
    for (int j = 0; j < 4; j++)
        yb[(size_t)(qh * 4 + j) * E + krow] = out_reg[j];
}

// ---------------- launch -----------------------------------------------------
extern "C" void kernel_launch(void* const* d_in, const int* in_sizes, int n_in,
                              void* d_out, int out_size) {
    (void)in_sizes; (void)n_in; (void)out_size;
    const float* x    = (const float*)d_in[0];
    const int*   mask = (const int*)  d_in[1];
    const float* wq   = (const float*)d_in[2];
    const float* wk   = (const float*)d_in[3];
    const float* wv   = (const float*)d_in[4];
    const float* ws   = (const float*)d_in[5];
    const float* bs   = (const float*)d_in[6];
    float* y = (float*)d_out;

    const int proj_smem = (64 * PKS + 128 * PWS) * 4;
    cudaFuncSetAttribute(proj_mma_kernel,
                         cudaFuncAttributeMaxDynamicSharedMemorySize, proj_smem);
    const int smem_bytes = (2 * CH * KS + QT * SS + 2 * QT * QS) * 4 + 2048 + 256;
    cudaFuncSetAttribute(attn7_kernel,
                         cudaFuncAttributeMaxDynamicSharedMemorySize, smem_bytes);

    dim3 gp(16, 128, 3);
    proj_mma_kernel<<<gp, 256, proj_smem>>>(x, wq, wk, wv);
    sel_kernel<<<B, 128>>>(x, ws, bs);
    dim3 ga(T / QT, B);
    attn7_kernel<<<ga, THR, smem_bytes>>>(mask, y);
}

// round 17
// speedup vs baseline: 1.1607x; 1.1607x over previous
#include <cuda_runtime.h>
#include <cuda_bf16.h>
#include <cstdint>

#define B 8
#define T 1024
#define E 128
#define H 8
#define HB (H*B)
#define SCALE 0.08838834764831845f   // 1/sqrt(128)
#define NEGV (-1e9f)
#define QT 16
#define CH 128
#define SS 1028                       // padded score row stride (floats)
#define THR 512
#define PKS 132                       // proj x tile stride
#define PWS 68                        // proj wraw stride ([k][n] layout)
#define KPP 68                        // K plane row stride (bf16x2 pairs, padded)
#define QPP 68                        // Q plane row stride (pairs, padded)
#define KBUF (CH*KPP)                 // 8704 u32 per K plane buffer

// ---------------- scratch (static device globals; no allocs allowed) --------
__device__ float    g_q[HB * T * E];
__device__ float    g_v[HB * T * E];
__device__ uint32_t g_khi[HB * T * E / 2];   // bf16x2 pairs (hi plane)
__device__ uint32_t g_klo[HB * T * E / 2];   // bf16x2 pairs (lo plane)
__device__ float    g_sel[B * H];

// ---------------- helpers ----------------------------------------------------
__device__ __forceinline__ void cpa16(uint32_t dst, const void* src) {
    asm volatile("cp.async.cg.shared.global [%0], [%1], 16;\n" :: "r"(dst), "l"(src));
}
__device__ __forceinline__ void cpa_commit() {
    asm volatile("cp.async.commit_group;\n");
}
__device__ __forceinline__ void cpa_wait0() {
    asm volatile("cp.async.wait_group 0;\n");
}
__device__ __forceinline__ uint32_t tf32_rna(float x) {
    uint32_t r;
    asm("cvt.rna.tf32.f32 %0, %1;" : "=r"(r) : "f"(x));
    return r;
}
__device__ __forceinline__ void mma_tf32(float& c0, float& c1, float& c2, float& c3,
                                         uint32_t a0, uint32_t a1, uint32_t a2, uint32_t a3,
                                         uint32_t b0, uint32_t b1) {
    asm("mma.sync.aligned.m16n8k8.row.col.f32.tf32.tf32.f32 "
        "{%0,%1,%2,%3}, {%4,%5,%6,%7}, {%8,%9}, {%0,%1,%2,%3};"
        : "+f"(c0), "+f"(c1), "+f"(c2), "+f"(c3)
        : "r"(a0), "r"(a1), "r"(a2), "r"(a3), "r"(b0), "r"(b1));
}
__device__ __forceinline__ void mma_bf16(float& c0, float& c1, float& c2, float& c3,
                                         uint32_t a0, uint32_t a1, uint32_t a2, uint32_t a3,
                                         uint32_t b0, uint32_t b1) {
    asm("mma.sync.aligned.m16n8k16.row.col.f32.bf16.bf16.f32 "
        "{%0,%1,%2,%3}, {%4,%5,%6,%7}, {%8,%9}, {%0,%1,%2,%3};"
        : "+f"(c0), "+f"(c1), "+f"(c2), "+f"(c3)
        : "r"(a0), "r"(a1), "r"(a2), "r"(a3), "r"(b0), "r"(b1));
}
// split (f0 even-col, f1 odd-col) into packed bf16x2 hi and lo planes
__device__ __forceinline__ void bf16_split2(float f0, float f1,
                                            uint32_t& hi, uint32_t& lo) {
    asm("cvt.rn.bf16x2.f32 %0, %1, %2;" : "=r"(hi) : "f"(f1), "f"(f0));
    __nv_bfloat162 h = *reinterpret_cast<__nv_bfloat162*>(&hi);
    float r0 = f0 - __bfloat162float(h.x);
    float r1 = f1 - __bfloat162float(h.y);
    asm("cvt.rn.bf16x2.f32 %0, %1, %2;" : "=r"(lo) : "f"(r1), "f"(r0));
}

// ---------------- projection GEMM via 3xTF32 mma ------------------------------
// z=0 -> Q f32; z=1 -> K bf16 hi/lo planes; z=2 -> V f32.
__global__ void __launch_bounds__(256) proj_mma_kernel(const float* __restrict__ x,
                                                       const float* __restrict__ wq,
                                                       const float* __restrict__ wk,
                                                       const float* __restrict__ wv) {
    const float* w;
    float* out = nullptr;
    if (blockIdx.z == 0)      { w = wq; out = g_q; }
    else if (blockIdx.z == 1) { w = wk; }
    else                      { w = wv; out = g_v; }

    extern __shared__ float psm[];
    float* xs   = psm;                 // 64 * PKS
    float* wraw = psm + 64 * PKS;      // 128 * PWS ([k][n])

    const int tid  = threadIdx.x;
    const int wid  = tid >> 5;
    const int lane = tid & 31;
    const int mw   = wid >> 1;
    const int nw   = wid & 1;
    const int g    = lane >> 2;
    const int tig  = lane & 3;
    const int m0 = blockIdx.y * 64;
    const int n0 = blockIdx.x * 64;

    #pragma unroll
    for (int i = 0; i < 8; i++) {
        int f = tid + i * 256;
        int row = f >> 5, c4 = f & 31;
        *(float4*)&xs[row * PKS + c4 * 4] =
            *(const float4*)(x + (size_t)(m0 + row) * 128 + c4 * 4);
    }
    #pragma unroll
    for (int i = 0; i < 8; i++) {
        int f = tid + i * 256;
        int k = f >> 4, c = f & 15;
        *(float4*)&wraw[k * PWS + c * 4] =
            *(const float4*)(w + (size_t)k * 1024 + n0 + c * 4);
    }
    __syncthreads();

    float c0[4], c1[4], c2[4], c3[4];
    #pragma unroll
    for (int t8 = 0; t8 < 4; t8++) { c0[t8] = c1[t8] = c2[t8] = c3[t8] = 0.f; }

    const float* Ar0 = xs + (mw * 16 + g) * PKS + tig;
    const float* Ar1 = xs + (mw * 16 + g + 8) * PKS + tig;
    const int nbase = nw * 32 + g;

    #pragma unroll
    for (int e0 = 0; e0 < 128; e0 += 8) {
        float a0f = Ar0[e0], a1f = Ar1[e0], a2f = Ar0[e0 + 4], a3f = Ar1[e0 + 4];
        uint32_t ah0 = tf32_rna(a0f), ah1 = tf32_rna(a1f);
        uint32_t ah2 = tf32_rna(a2f), ah3 = tf32_rna(a3f);
        uint32_t al0 = tf32_rna(a0f - __uint_as_float(ah0));
        uint32_t al1 = tf32_rna(a1f - __uint_as_float(ah1));
        uint32_t al2 = tf32_rna(a2f - __uint_as_float(ah2));
        uint32_t al3 = tf32_rna(a3f - __uint_as_float(ah3));
        const float* Wr0 = wraw + (tig + e0) * PWS + nbase;
        const float* Wr1 = wraw + (tig + 4 + e0) * PWS + nbase;
        #pragma unroll
        for (int t8 = 0; t8 < 4; t8++) {
            float b0f = Wr0[t8 * 8];
            float b1f = Wr1[t8 * 8];
            uint32_t bh0 = tf32_rna(b0f), bh1 = tf32_rna(b1f);
            uint32_t bl0 = tf32_rna(b0f - __uint_as_float(bh0));
            uint32_t bl1 = tf32_rna(b1f - __uint_as_float(bh1));
            mma_tf32(c0[t8], c1[t8], c2[t8], c3[t8], ah0, ah1, ah2, ah3, bl0, bl1);
            mma_tf32(c0[t8], c1[t8], c2[t8], c3[t8], al0, al1, al2, al3, bh0, bh1);
            mma_tf32(c0[t8], c1[t8], c2[t8], c3[t8], ah0, ah1, ah2, ah3, bh0, bh1);
        }
    }

    const int bb = m0 >> 10;
    const int tbase = (m0 & 1023) + mw * 16;
    if (blockIdx.z == 1) {
        // K: write bf16 hi/lo planes (pair index = e/2)
        #pragma unroll
        for (int t8 = 0; t8 < 4; t8++) {
            int n = n0 + nw * 32 + t8 * 8 + 2 * tig;
            int hh = n >> 7, e = n & 127;
            size_t p0 = ((size_t)(hh * B + bb) * T + tbase + g) * 64 + (e >> 1);
            size_t p1 = ((size_t)(hh * B + bb) * T + tbase + g + 8) * 64 + (e >> 1);
            uint32_t hi, lo;
            bf16_split2(c0[t8], c1[t8], hi, lo);
            g_khi[p0] = hi; g_klo[p0] = lo;
            bf16_split2(c2[t8], c3[t8], hi, lo);
            g_khi[p1] = hi; g_klo[p1] = lo;
        }
    } else {
        #pragma unroll
        for (int t8 = 0; t8 < 4; t8++) {
            int n = n0 + nw * 32 + t8 * 8 + 2 * tig;
            int hh = n >> 7, e = n & 127;
            float* o0 = out + ((size_t)(hh * B + bb) * T + tbase + g) * E + e;
            float* o1 = out + ((size_t)(hh * B + bb) * T + tbase + g + 8) * E + e;
            *(float2*)o0 = make_float2(c0[t8], c1[t8]);
            *(float2*)o1 = make_float2(c2[t8], c3[t8]);
        }
    }
}

// ---------------- head-gate softmax (unchanged) ------------------------------
__global__ void __launch_bounds__(128) sel_kernel(const float* __restrict__ x,
                                                  const float* __restrict__ w_s,
                                                  const float* __restrict__ b_s) {
    const int b = blockIdx.x;
    const int tid = threadIdx.x;
    __shared__ float mean_sh[128];
    __shared__ float logit_sh[8];

    const float* xb = x + (size_t)b * T * E;
    float s = 0.f;
    for (int t = 0; t < T; t++) s += xb[(size_t)t * E + tid];
    mean_sh[tid] = s * (1.0f / 1024.0f);
    __syncthreads();
    if (tid < H) {
        float l = b_s[tid];
        const float* wr = w_s + tid * E;
        #pragma unroll 4
        for (int e = 0; e < E; e++) l = fmaf(mean_sh[e], wr[e], l);
        logit_sh[tid] = l;
    }
    __syncthreads();
    if (tid == 0) {
        float mx = logit_sh[0];
        for (int h = 1; h < H; h++) mx = fmaxf(mx, logit_sh[h]);
        float ex[H]; float den = 0.f;
        for (int h = 0; h < H; h++) { ex[h] = expf(logit_sh[h] - mx); den += ex[h]; }
        float inv = 1.0f / den;
        for (int h = 0; h < H; h++) g_sel[b * H + h] = ex[h] * inv;
    }
}

// ---------------- fused attention: 4-term bf16x2 mma scores ------------------
// smem (u32 units): Khi[2][KBUF] | Klo[2][KBUF] | s_sh | Qh | Ql | mb | misc
__global__ void __launch_bounds__(THR) attn8_kernel(const int* __restrict__ mask,
                                                    float* __restrict__ y) {
    extern __shared__ uint32_t smu[];
    uint32_t* Khi   = smu;                           // 2*KBUF = 17408
    uint32_t* Klo   = smu + 2 * KBUF;                // 17408
    float*    s_sh  = (float*)(smu + 4 * KBUF);      // 16448
    uint32_t* Qh    = smu + 4 * KBUF + QT * SS;      // 1088
    uint32_t* Ql    = Qh + QT * QPP;                 // 1088
    uint32_t* mb    = Ql + QT * QPP;                 // 512
    float*    tau_sh = (float*)(mb + 512);           // 16
    float*    sel_sh = tau_sh + 16;                  // 8
    int*      qscan  = (int*)(sel_sh + 8);           // 17
    int*      full_sh= qscan + 17;                   // 16
    int*      flat   = (int*)Khi;                    // aliases K hi buffers (AV)

    const int b    = blockIdx.y;
    const int q0   = blockIdx.x * QT;
    const int tid  = threadIdx.x;
    const int krow = tid & 127;          // e in AV phase
    const int qh   = tid >> 7;           // q quartet (AV phase)
    const int wid  = tid >> 5;           // warp: mma strip / sparsemax row
    const int lane = tid & 31;
    const int g    = lane >> 2;
    const int tig  = lane & 3;
    const int kb   = wid * 8;            // this warp's 8 k-rows within chunk

    float out_reg[4] = {0.f, 0.f, 0.f, 0.f};
    if (tid < H) sel_sh[tid] = g_sel[b * H + tid];

    // ---- mask bitwords (bit set = masked) ----
    {
        int q = tid >> 5, wk = tid & 31;
        const int4* p = (const int4*)(mask + ((size_t)b * T + q0 + q) * T + wk * 32);
        uint32_t word = 0;
        #pragma unroll
        for (int i = 0; i < 8; i++) {
            int4 v = p[i];
            word |= (uint32_t)(v.x != 0) << (i * 4 + 0);
            word |= (uint32_t)(v.y != 0) << (i * 4 + 1);
            word |= (uint32_t)(v.z != 0) << (i * 4 + 2);
            word |= (uint32_t)(v.w != 0) << (i * 4 + 3);
        }
        mb[tid] = word;
    }
    __syncthreads();
    if (tid < QT) {
        int c = 0;
        #pragma unroll
        for (int i = 0; i < 32; i++) c += __popc(mb[tid * 32 + i]);
        full_sh[tid] = (c == 1024);
    }

    for (int h = 0; h < H; h++) {
        const size_t hb = (size_t)(h * B + b);
        const uint32_t* KHg = g_khi + (hb * T) * 64;   // pair units
        const uint32_t* KLg = g_klo + (hb * T) * 64;

        // Q tile -> bf16 hi/lo packed planes (once per head)
        {
            int j = tid >> 5, c4 = tid & 31;
            float4 qv = ((const float4*)(g_q + (hb * T + q0 + j) * E))[c4];
            uint32_t h0, l0, h1, l1;
            bf16_split2(qv.x, qv.y, h0, l0);
            bf16_split2(qv.z, qv.w, h1, l1);
            Qh[j * QPP + 2 * c4]     = h0;
            Qh[j * QPP + 2 * c4 + 1] = h1;
            Ql[j * QPP + 2 * c4]     = l0;
            Ql[j * QPP + 2 * c4 + 1] = l1;
        }

        // prefetch chunk 0 (both planes) into buffer 0
        {
            uint32_t dh = (uint32_t)__cvta_generic_to_shared(Khi);
            uint32_t dl = (uint32_t)__cvta_generic_to_shared(Klo);
            #pragma unroll
            for (int i = 0; i < 4; i++) {
                int f = tid + i * THR;      // 0..2047 16B units
                int r = f >> 4, u = f & 15;
                cpa16(dh + (uint32_t)(r * KPP + u * 4) * 4, KHg + r * 64 + u * 4);
                cpa16(dl + (uint32_t)(r * KPP + u * 4) * 4, KLg + r * 64 + u * 4);
            }
            cpa_commit();
        }

        for (int c = 0; c < 8; c++) {
            cpa_wait0();
            __syncthreads();          // chunk c visible; other buffer free
            if (c < 7) {              // prefetch next chunk (both planes)
                int nb = (c + 1) & 1;
                uint32_t dh = (uint32_t)__cvta_generic_to_shared(Khi + nb * KBUF);
                uint32_t dl = (uint32_t)__cvta_generic_to_shared(Klo + nb * KBUF);
                const uint32_t* sh = KHg + (size_t)(c + 1) * CH * 64;
                const uint32_t* sl = KLg + (size_t)(c + 1) * CH * 64;
                #pragma unroll
                for (int i = 0; i < 4; i++) {
                    int f = tid + i * THR;
                    int r = f >> 4, u = f & 15;
                    cpa16(dh + (uint32_t)(r * KPP + u * 4) * 4, sh + r * 64 + u * 4);
                    cpa16(dl + (uint32_t)(r * KPP + u * 4) * 4, sl + r * 64 + u * 4);
                }
                cpa_commit();
            }

            // ---- 4-term bf16x2 mma: A = Q planes, B = this warp's 8 K rows ----
            const uint32_t* Bh = Khi + (c & 1) * KBUF + (kb + g) * KPP + tig;
            const uint32_t* Bl = Klo + (c & 1) * KBUF + (kb + g) * KPP + tig;
            const uint32_t* A0h = Qh + g * QPP + tig;
            const uint32_t* A1h = Qh + (g + 8) * QPP + tig;
            const uint32_t* A0l = Ql + g * QPP + tig;
            const uint32_t* A1l = Ql + (g + 8) * QPP + tig;
            float hh0 = 0.f, hh1 = 0.f, hh2 = 0.f, hh3 = 0.f;
            float hl0 = 0.f, hl1 = 0.f, hl2 = 0.f, hl3 = 0.f;
            float lh0 = 0.f, lh1 = 0.f, lh2 = 0.f, lh3 = 0.f;
            float ll0 = 0.f, ll1 = 0.f, ll2 = 0.f, ll3 = 0.f;
            #pragma unroll
            for (int p = 0; p < 64; p += 8) {     // 8 k16-steps (pair units)
                uint32_t ah0 = A0h[p],     ah1 = A1h[p];
                uint32_t ah2 = A0h[p + 4], ah3 = A1h[p + 4];
                uint32_t al0 = A0l[p],     al1 = A1l[p];
                uint32_t al2 = A0l[p + 4], al3 = A1l[p + 4];
                uint32_t bh0 = Bh[p], bh1 = Bh[p + 4];
                uint32_t bl0 = Bl[p], bl1 = Bl[p + 4];
                mma_bf16(hh0, hh1, hh2, hh3, ah0, ah1, ah2, ah3, bh0, bh1);
                mma_bf16(hl0, hl1, hl2, hl3, ah0, ah1, ah2, ah3, bl0, bl1);
                mma_bf16(lh0, lh1, lh2, lh3, al0, al1, al2, al3, bh0, bh1);
                mma_bf16(ll0, ll1, ll2, ll3, al0, al1, al2, al3, bl0, bl1);
            }
            float c0 = hh0 + ((hl0 + lh0) + ll0);
            float c1 = hh1 + ((hl1 + lh1) + ll1);
            float c2 = hh2 + ((hl2 + lh2) + ll2);
            float c3 = hh3 + ((hl3 + lh3) + ll3);

            // epilogue: C rows = q (g, g+8), cols = k (kb+2tig, +1); mask + scale
            {
                const int kg0 = c * CH + kb + 2 * tig;
                const int kg1 = kg0 + 1;
                const int qa  = g;
                const int qb  = g + 8;
                const int wix0 = kg0 >> 5, bix0 = kg0 & 31;
                const int wix1 = kg1 >> 5, bix1 = kg1 & 31;
                uint32_t wa0 = mb[qa * 32 + wix0];
                uint32_t wa1 = mb[qa * 32 + wix1];
                uint32_t wb0 = mb[qb * 32 + wix0];
                uint32_t wb1 = mb[qb * 32 + wix1];
                s_sh[qa * SS + kg0] = ((wa0 >> bix0) & 1u) ? NEGV : c0 * SCALE;
                s_sh[qa * SS + kg1] = ((wa1 >> bix1) & 1u) ? NEGV : c1 * SCALE;
                s_sh[qb * SS + kg0] = ((wb0 >> bix0) & 1u) ? NEGV : c2 * SCALE;
                s_sh[qb * SS + kg1] = ((wb1 >> bix1) & 1u) ? NEGV : c3 * SCALE;
            }
        }
        __syncthreads();              // all scores in s_sh; K buffers free

        // ---- load this warp's score row into registers (one pass) ----
        float4 vr[8];
        {
            const float4* s4 = (const float4*)(s_sh + wid * SS);
            #pragma unroll
            for (int i = 0; i < 8; i++) vr[i] = s4[lane + i * 32];
        }

        // ---- sparsemax (Michelot), register-resident ----
        float tau;
        int excl, cnt;
        {
            if (full_sh[wid]) {
                tau = 3.0e38f;
            } else {
                tau = -1.0e8f;
                int prev = -1;
                for (int it = 0; it < 64; it++) {
                    float ls = 0.f; int lc = 0;
                    #pragma unroll
                    for (int i = 0; i < 8; i++) {
                        float4 v = vr[i];
                        if (v.x > tau) { ls += v.x; lc++; }
                        if (v.y > tau) { ls += v.y; lc++; }
                        if (v.z > tau) { ls += v.z; lc++; }
                        if (v.w > tau) { ls += v.w; lc++; }
                    }
                    #pragma unroll
                    for (int o = 16; o; o >>= 1) {
                        ls += __shfl_xor_sync(0xffffffffu, ls, o);
                        lc += __shfl_xor_sync(0xffffffffu, lc, o);
                    }
                    if (lc == prev || lc == 0) break;
                    tau = (ls - 1.f) / (float)lc;
                    prev = lc;
                }
            }
            if (lane == 0) tau_sh[wid] = tau;

            cnt = 0;
            #pragma unroll
            for (int i = 0; i < 8; i++) {
                float4 v = vr[i];
                cnt += (v.x > tau) + (v.y > tau) + (v.z > tau) + (v.w > tau);
            }
            int incl = cnt;
            #pragma unroll
            for (int o = 1; o < 32; o <<= 1) {
                int t = __shfl_up_sync(0xffffffffu, incl, o);
                if (lane >= o) incl += t;
            }
            excl = incl - cnt;
            if (lane == 31) qscan[wid + 1] = incl;
        }
        __syncthreads();
        if (tid == 0) {
            qscan[0] = 0;
            #pragma unroll
            for (int i = 1; i <= 16; i++) qscan[i] += qscan[i - 1];
        }
        __syncthreads();

        // ---- flat support list (aliases K hi buffers; q-contiguous) ----
        if (cnt > 0) {
            int off = qscan[wid] + excl;
            #pragma unroll
            for (int i = 0; i < 8; i++) {
                int kbase = (lane + i * 32) * 4;
                float4 v = vr[i];
                if (v.x > tau) flat[off++] = kbase;
                if (v.y > tau) flat[off++] = kbase + 1;
                if (v.z > tau) flat[off++] = kbase + 2;
                if (v.w > tau) flat[off++] = kbase + 3;
            }
        }
        __syncthreads();

        // ---- sparse AV: register accumulation, thread = (e, q quartet) ----
        {
            const float selh = sel_sh[h];
            const float* Vg = g_v + hb * T * E + krow;   // krow == e
            #pragma unroll
            for (int j = 0; j < 4; j++) {
                int q = qh * 4 + j;
                float tq = tau_sh[q];
                int s = qscan[q], e = qscan[q + 1];
                const float* sq = s_sh + q * SS;
                float a0 = 0.f, a1 = 0.f;
                int i = s;
                for (; i + 2 <= e; i += 2) {
                    int k0 = flat[i], k1 = flat[i + 1];
                    float p0 = sq[k0] - tq;
                    float p1 = sq[k1] - tq;
                    a0 = fmaf(p0, Vg[(size_t)k0 * E], a0);
                    a1 = fmaf(p1, Vg[(size_t)k1 * E], a1);
                }
                if (i < e) {
                    int k0 = flat[i];
                    a0 = fmaf(sq[k0] - tq, Vg[(size_t)k0 * E], a0);
                }
                out_reg[j] = fmaf(selh, a0 + a1, out_reg[j]);
            }
        }
        __syncthreads();   // flat (K buf), s_sh, Q planes reused next head
    }

    // ---- epilogue: direct global store ----
    float* yb = y + ((size_t)b * T + q0) * E;
    #pragma unroll
    for (int j = 0; j < 4; j++)
        yb[(size_t)(qh * 4 + j) * E + krow] = out_reg[j];
}

// ---------------- launch -----------------------------------------------------
extern "C" void kernel_launch(void* const* d_in, const int* in_sizes, int n_in,
                              void* d_out, int out_size) {
    (void)in_sizes; (void)n_in; (void)out_size;
    const float* x    = (const float*)d_in[0];
    const int*   mask = (const int*)  d_in[1];
    const float* wq   = (const float*)d_in[2];
    const float* wk   = (const float*)d_in[3];
    const float* wv   = (const float*)d_in[4];
    const float* ws   = (const float*)d_in[5];
    const float* bs   = (const float*)d_in[6];
    float* y = (float*)d_out;

    const int proj_smem = (64 * PKS + 128 * PWS) * 4;
    cudaFuncSetAttribute(proj_mma_kernel,
                         cudaFuncAttributeMaxDynamicSharedMemorySize, proj_smem);
    // 4*KBUF + s + 2 Q planes + mb + misc (u32 units)
    const int smem_u32 = 4 * KBUF + QT * SS + 2 * QT * QPP + 512 + 64;
    const int smem_bytes = smem_u32 * 4;
    cudaFuncSetAttribute(attn8_kernel,
                         cudaFuncAttributeMaxDynamicSharedMemorySize, smem_bytes);

    dim3 gp(16, 128, 3);
    proj_mma_kernel<<<gp, 256, proj_smem>>>(x, wq, wk, wv);
    sel_kernel<<<B, 128>>>(x, ws, bs);
    dim3 ga(T / QT, B);
    attn8_kernel<<<ga, THR, smem_bytes>>>(mask, y);
}